// round 13
// baseline (speedup 1.0000x reference)
#include <cuda_runtime.h>
#include <cuda_bf16.h>
#include <cstdint>

// Problem constants (fixed by the reference)
#define NB       50          // n_boundaries
#define ELEN     51          // embd rows
#define EDIM     50          // embd dim
#define ODIM     50          // out dim
#define HID      101         // MLP width = 2*EDIM+1
#define W2P      52          // padded w2t row (13 float4)
#define MAXN     (16*65536)  // B*N

// ---------------- device scratch (static; no allocations) ----------------
__device__ float d_base[ELEN * HID];   // base[b][j] = embd[b]@W1a + embd[b+1]@W1b + b1   (b in 1..49 used)
__device__ float d_w2t [HID * W2P];    // w2t[j][o] = w2[o][j], padded with zeros
__device__ float d_c   [HID];          // c[j] = w1[j][100]
__device__ float d_b2  [ODIM];
__device__ int   d_count;
__device__ int2  d_compact[MAXN];      // {elem | (idx<<20), bits(dist)}

// ---------------- kernel 0: fold w1/b1/embd into per-bucket bases --------
__global__ void precompute_kernel(const float* __restrict__ embd,
                                  const float* __restrict__ w1,
                                  const float* __restrict__ b1,
                                  const float* __restrict__ w2,
                                  const float* __restrict__ b2)
{
    int tid = blockIdx.x * blockDim.x + threadIdx.x;
    int stride = gridDim.x * blockDim.x;

    // base table: 51*101 entries, 100 MACs each (only b=1..49 consumed)
    for (int t = tid; t < ELEN * HID; t += stride) {
        int b = t / HID, j = t % HID;
        int bi0 = b;
        int bi1 = (b + 1 < ELEN) ? (b + 1) : (ELEN - 1);
        float s = b1[j];
        #pragma unroll 10
        for (int k = 0; k < EDIM; k++) {
            s = fmaf(embd[bi0 * EDIM + k], w1[j * HID + k],        s);
            s = fmaf(embd[bi1 * EDIM + k], w1[j * HID + EDIM + k], s);
        }
        d_base[t] = s;
    }
    // transposed, padded w2
    for (int t = tid; t < HID * W2P; t += stride) {
        int j = t / W2P, o = t % W2P;
        d_w2t[t] = (o < ODIM) ? w2[o * HID + j] : 0.0f;
    }
    for (int t = tid; t < HID;  t += stride) d_c[t]  = w1[t * HID + (HID - 1)];
    for (int t = tid; t < ODIM; t += stride) d_b2[t] = b2[t];
    if (tid == 0) d_count = 0;   // reset compaction counter every launch
}

// ---------------- kernel 1: bucketize, write OOB rows, compact in-range --
__global__ void __launch_bounds__(256)
pass1_kernel(const float* __restrict__ x,
             const float* __restrict__ bnds,
             const float* __restrict__ oob,
             float* __restrict__ out, int n)
{
    __shared__ float s_b[NB];
    __shared__ float s_oob[2 * ODIM];
    int tid = threadIdx.x;
    if (tid < NB)        s_b[tid]   = bnds[tid];
    if (tid < 2 * ODIM)  s_oob[tid] = oob[tid];
    __syncthreads();

    int i = blockIdx.x * blockDim.x + tid;
    bool valid = (i < n);
    float xv = valid ? x[i] : 0.0f;

    // searchsorted side='left': idx = #{k : b[k] < xv}
    int idx = 0;
    #pragma unroll
    for (int k = 0; k < NB; k++) idx += (s_b[k] < xv) ? 1 : 0;

    bool inr = valid && (idx > 0) && (idx < NB);

    if (valid && !inr) {
        // out-of-range: copy the constant row
        const float* src = s_oob + ((idx == NB) ? ODIM : 0);
        float* orow = out + (size_t)i * ODIM;   // 200B rows -> 8B aligned
        #pragma unroll
        for (int o = 0; o < ODIM; o += 2)
            *reinterpret_cast<float2*>(orow + o) = make_float2(src[o], src[o + 1]);
    }

    unsigned m = __ballot_sync(0xffffffffu, inr);
    if (inr) {
        float lo = s_b[idx - 1], hi = s_b[idx];
        float dist = (xv - lo) / (hi - lo);
        int lane = tid & 31;
        int leader = __ffs(m) - 1;
        int pos = 0;
        if (lane == leader) pos = atomicAdd(&d_count, __popc(m));
        pos = __shfl_sync(m, pos, leader);
        pos += __popc(m & ((1u << lane) - 1u));
        d_compact[pos] = make_int2(i | (idx << 20), __float_as_int(dist));
    }
}

// ---------------- kernel 2: fused MLP on compacted in-range elements -----
__global__ void __launch_bounds__(256, 2)
pass2_kernel(float* __restrict__ out)
{
    __shared__ float  s_base[ELEN * HID];       // 20.6 KB
    __shared__ float4 s_w2[HID * (W2P / 4)];    // 21.0 KB
    __shared__ float  s_c[HID];
    __shared__ float  s_b2[ODIM];

    {
        float* w2s = reinterpret_cast<float*>(s_w2);
        for (int t = threadIdx.x; t < ELEN * HID; t += blockDim.x) s_base[t] = d_base[t];
        for (int t = threadIdx.x; t < HID * W2P;  t += blockDim.x) w2s[t]    = d_w2t[t];
        for (int t = threadIdx.x; t < HID;        t += blockDim.x) s_c[t]    = d_c[t];
        for (int t = threadIdx.x; t < ODIM;       t += blockDim.x) s_b2[t]   = d_b2[t];
    }
    __syncthreads();

    int total = d_count;
    for (int t = blockIdx.x * blockDim.x + threadIdx.x; t < total;
         t += gridDim.x * blockDim.x) {
        int2 e = d_compact[t];
        int elem = e.x & 0xFFFFF;
        int b    = e.x >> 20;              // in [1,49]
        float dist = __int_as_float(e.y);

        float acc[ODIM];
        #pragma unroll
        for (int o = 0; o < ODIM; o++) acc[o] = s_b2[o];

        const float*  bb = s_base + b * HID;       // per-thread, stride 101 (conflict-free mod 32)
        #pragma unroll 2
        for (int j = 0; j < HID; j++) {
            float pre = fmaf(dist, s_c[j], bb[j]);
            // exact GELU: x * 0.5 * (1 + erf(x/sqrt(2)))
            float h = 0.5f * pre * (1.0f + erff(pre * 0.70710678118654752f));
            const float4* wr = s_w2 + j * (W2P / 4);   // warp-uniform -> LDS broadcast
            #pragma unroll
            for (int q = 0; q < 12; q++) {
                float4 w = wr[q];
                acc[4*q + 0] = fmaf(h, w.x, acc[4*q + 0]);
                acc[4*q + 1] = fmaf(h, w.y, acc[4*q + 1]);
                acc[4*q + 2] = fmaf(h, w.z, acc[4*q + 2]);
                acc[4*q + 3] = fmaf(h, w.w, acc[4*q + 3]);
            }
            float4 w = wr[12];
            acc[48] = fmaf(h, w.x, acc[48]);
            acc[49] = fmaf(h, w.y, acc[49]);
        }

        float* orow = out + (size_t)elem * ODIM;
        #pragma unroll
        for (int o = 0; o < ODIM; o += 2)
            *reinterpret_cast<float2*>(orow + o) = make_float2(acc[o], acc[o + 1]);
    }
}

// ---------------- launch ---------------------------------------------------
extern "C" void kernel_launch(void* const* d_in, const int* in_sizes, int n_in,
                              void* d_out, int out_size)
{
    // metadata order: x, boundaries, embd, embd_oob, w1, b1, w2, b2
    const float* x     = (const float*)d_in[0];
    const float* bnds  = (const float*)d_in[1];
    const float* embd  = (const float*)d_in[2];
    const float* oob   = (const float*)d_in[3];
    const float* w1    = (const float*)d_in[4];
    const float* b1    = (const float*)d_in[5];
    const float* w2    = (const float*)d_in[6];
    const float* b2    = (const float*)d_in[7];
    float* out = (float*)d_out;
    int n = in_sizes[0];   // B*N (x is (B,N,1))

    precompute_kernel<<<32, 256>>>(embd, w1, b1, w2, b2);
    pass1_kernel<<<(n + 255) / 256, 256>>>(x, bnds, oob, out, n);
    pass2_kernel<<<888, 256>>>(out);
}

// round 14
// speedup vs baseline: 1.0286x; 1.0286x over previous
#include <cuda_runtime.h>
#include <cuda_bf16.h>
#include <cstdint>

// Problem constants (fixed by the reference)
#define NB       50          // n_boundaries
#define ELEN     51          // embd rows
#define EDIM     50          // embd dim
#define ODIM     50          // out dim
#define HID      101         // MLP width = 2*EDIM+1
#define W2P      52          // padded w2t row (13 float4)
#define MAXN     (16*65536)  // B*N

// ---------------- device scratch (static; no allocations) ----------------
__device__ float d_base[ELEN * HID];   // base[b][j] = embd[b]@W1a + embd[b+1]@W1b + b1   (b in 1..49 used)
__device__ float d_w2t [HID * W2P];    // w2t[j][o] = w2[o][j], padded with zeros
__device__ float d_c   [HID];          // c[j] = w1[j][100]
__device__ float d_b2  [ODIM];
__device__ int   d_count;
__device__ int2  d_compact[MAXN];      // {elem | (idx<<20), bits(dist)}

// ---------------- kernel 0: fold w1/b1/embd into per-bucket bases --------
__global__ void precompute_kernel(const float* __restrict__ embd,
                                  const float* __restrict__ w1,
                                  const float* __restrict__ b1,
                                  const float* __restrict__ w2,
                                  const float* __restrict__ b2)
{
    int tid = blockIdx.x * blockDim.x + threadIdx.x;
    int stride = gridDim.x * blockDim.x;

    // base table: 51*101 entries, 100 MACs each (only b=1..49 consumed)
    for (int t = tid; t < ELEN * HID; t += stride) {
        int b = t / HID, j = t % HID;
        int bi0 = b;
        int bi1 = (b + 1 < ELEN) ? (b + 1) : (ELEN - 1);
        float s = b1[j];
        #pragma unroll 10
        for (int k = 0; k < EDIM; k++) {
            s = fmaf(embd[bi0 * EDIM + k], w1[j * HID + k],        s);
            s = fmaf(embd[bi1 * EDIM + k], w1[j * HID + EDIM + k], s);
        }
        d_base[t] = s;
    }
    // transposed, padded w2
    for (int t = tid; t < HID * W2P; t += stride) {
        int j = t / W2P, o = t % W2P;
        d_w2t[t] = (o < ODIM) ? w2[o * HID + j] : 0.0f;
    }
    for (int t = tid; t < HID;  t += stride) d_c[t]  = w1[t * HID + (HID - 1)];
    for (int t = tid; t < ODIM; t += stride) d_b2[t] = b2[t];
    if (tid == 0) d_count = 0;   // reset compaction counter every launch
}

// ---------------- kernel 1: bucketize, write OOB rows, compact in-range --
__global__ void __launch_bounds__(256)
pass1_kernel(const float* __restrict__ x,
             const float* __restrict__ bnds,
             const float* __restrict__ oob,
             float* __restrict__ out, int n)
{
    __shared__ float s_b[NB];
    __shared__ float s_oob[2 * ODIM];
    int tid = threadIdx.x;
    if (tid < NB)        s_b[tid]   = bnds[tid];
    if (tid < 2 * ODIM)  s_oob[tid] = oob[tid];
    __syncthreads();

    int i = blockIdx.x * blockDim.x + tid;
    bool valid = (i < n);
    float xv = valid ? x[i] : 0.0f;

    // searchsorted side='left': idx = #{k : b[k] < xv}
    int idx = 0;
    #pragma unroll
    for (int k = 0; k < NB; k++) idx += (s_b[k] < xv) ? 1 : 0;

    bool inr = valid && (idx > 0) && (idx < NB);

    if (valid && !inr) {
        // out-of-range: copy the constant row
        const float* src = s_oob + ((idx == NB) ? ODIM : 0);
        float* orow = out + (size_t)i * ODIM;   // 200B rows -> 8B aligned
        #pragma unroll
        for (int o = 0; o < ODIM; o += 2)
            *reinterpret_cast<float2*>(orow + o) = make_float2(src[o], src[o + 1]);
    }

    unsigned m = __ballot_sync(0xffffffffu, inr);
    if (inr) {
        float lo = s_b[idx - 1], hi = s_b[idx];
        float dist = (xv - lo) / (hi - lo);
        int lane = tid & 31;
        int leader = __ffs(m) - 1;
        int pos = 0;
        if (lane == leader) pos = atomicAdd(&d_count, __popc(m));
        pos = __shfl_sync(m, pos, leader);
        pos += __popc(m & ((1u << lane) - 1u));
        d_compact[pos] = make_int2(i | (idx << 20), __float_as_int(dist));
    }
}

// ---------------- kernel 2: fused MLP on compacted in-range elements -----
__global__ void __launch_bounds__(256, 2)
pass2_kernel(float* __restrict__ out)
{
    __shared__ float  s_base[ELEN * HID];       // 20.6 KB
    __shared__ float4 s_w2[HID * (W2P / 4)];    // 21.0 KB
    __shared__ float  s_c[HID];
    __shared__ float  s_b2[ODIM];

    {
        float* w2s = reinterpret_cast<float*>(s_w2);
        for (int t = threadIdx.x; t < ELEN * HID; t += blockDim.x) s_base[t] = d_base[t];
        for (int t = threadIdx.x; t < HID * W2P;  t += blockDim.x) w2s[t]    = d_w2t[t];
        for (int t = threadIdx.x; t < HID;        t += blockDim.x) s_c[t]    = d_c[t];
        for (int t = threadIdx.x; t < ODIM;       t += blockDim.x) s_b2[t]   = d_b2[t];
    }
    __syncthreads();

    int total = d_count;
    for (int t = blockIdx.x * blockDim.x + threadIdx.x; t < total;
         t += gridDim.x * blockDim.x) {
        int2 e = d_compact[t];
        int elem = e.x & 0xFFFFF;
        int b    = e.x >> 20;              // in [1,49]
        float dist = __int_as_float(e.y);

        float acc[ODIM];
        #pragma unroll
        for (int o = 0; o < ODIM; o++) acc[o] = s_b2[o];

        const float*  bb = s_base + b * HID;       // per-thread, stride 101 (conflict-free mod 32)
        #pragma unroll 2
        for (int j = 0; j < HID; j++) {
            float pre = fmaf(dist, s_c[j], bb[j]);
            // exact GELU: x * 0.5 * (1 + erf(x/sqrt(2)))
            float h = 0.5f * pre * (1.0f + erff(pre * 0.70710678118654752f));
            const float4* wr = s_w2 + j * (W2P / 4);   // warp-uniform -> LDS broadcast
            #pragma unroll
            for (int q = 0; q < 12; q++) {
                float4 w = wr[q];
                acc[4*q + 0] = fmaf(h, w.x, acc[4*q + 0]);
                acc[4*q + 1] = fmaf(h, w.y, acc[4*q + 1]);
                acc[4*q + 2] = fmaf(h, w.z, acc[4*q + 2]);
                acc[4*q + 3] = fmaf(h, w.w, acc[4*q + 3]);
            }
            float4 w = wr[12];
            acc[48] = fmaf(h, w.x, acc[48]);
            acc[49] = fmaf(h, w.y, acc[49]);
        }

        float* orow = out + (size_t)elem * ODIM;
        #pragma unroll
        for (int o = 0; o < ODIM; o += 2)
            *reinterpret_cast<float2*>(orow + o) = make_float2(acc[o], acc[o + 1]);
    }
}

// ---------------- launch ---------------------------------------------------
extern "C" void kernel_launch(void* const* d_in, const int* in_sizes, int n_in,
                              void* d_out, int out_size)
{
    // metadata order: x, boundaries, embd, embd_oob, w1, b1, w2, b2
    const float* x     = (const float*)d_in[0];
    const float* bnds  = (const float*)d_in[1];
    const float* embd  = (const float*)d_in[2];
    const float* oob   = (const float*)d_in[3];
    const float* w1    = (const float*)d_in[4];
    const float* b1    = (const float*)d_in[5];
    const float* w2    = (const float*)d_in[6];
    const float* b2    = (const float*)d_in[7];
    float* out = (float*)d_out;
    int n = in_sizes[0];   // B*N (x is (B,N,1))

    precompute_kernel<<<32, 256>>>(embd, w1, b1, w2, b2);
    pass1_kernel<<<(n + 255) / 256, 256>>>(x, bnds, oob, out, n);
    pass2_kernel<<<888, 256>>>(out);
}